// round 16
// baseline (speedup 1.0000x reference)
#include <cuda_runtime.h>
#include <cstdint>

// Problem constants (fixed by reference)
#define NN    16384   // n_nodes
#define D_IN  128
#define D_H   64
#define BB    4096    // minibatch

// ---------------------------------------------------------------------------
// Single fused kernel: one block (4 warps) per output row.
//   out[i,:] = ppr[idx[i],:] @ (X @ W + b)
//            = (ppr_row_sparse @ X) @ W + rowsum * b     (TOPK<=128 nonzeros)
//
//  0. idx dtype detect (odd words of entries 0..255 — in-bounds for both
//     int32 [4096 words] and int64 [8192 words]; P(false|int32)~0).
//  1. Scan + inline process, ballot-per-PAIR: per warp 8 uint4 in flight
//     (__ldcs). Two ballots per uint4 — (x|y) and (z|w) — processed one
//     pair at a time so only 3 shfl temporaries are live per hit body
//     (R15's per-uint4 ballot held 5 -> regs 70, occ collapse). Values are
//     nonneg with exact +0.0f zeros, so integer-OR tests are exact. Each
//     hit: broadcast (vx, vy, j) and all lanes run warp-uniform predicated
//     coalesced L2-hot FMA batches: acc4 += v * X4[col*32 + lane].
//  2. Combine warps -> sT[128], rowsum.
//  3. Epilogue (validated R13): thread = (column-quad, k-group): 16 LDG.128
//     of W + 64 FMA, smem k-group reduction, + rowsum*b.
// ---------------------------------------------------------------------------
__global__ void __launch_bounds__(128) fused_kernel(const float* __restrict__ ppr,
                                                    const float* __restrict__ X,
                                                    const float* __restrict__ W,
                                                    const float* __restrict__ b,
                                                    const int* __restrict__ idx32,
                                                    float* __restrict__ out) {
    __shared__ float red[4][D_IN];
    __shared__ float rsum[4];
    __shared__ float sT[D_IN];
    __shared__ float part[8][D_H];     // k-group partials
    __shared__ int   s_is64;

    const int i    = blockIdx.x;
    const int tid  = threadIdx.x;
    const int lane = tid & 31;
    const int warp = tid >> 5;

    // ---- Stage 0: dtype detect + row fetch ----
    if (tid == 0) s_is64 = 1;
    __syncthreads();
    if ((idx32[2 * tid + 1] | idx32[2 * (tid + 128) + 1]) != 0) s_is64 = 0;
    __syncthreads();
    const int row = s_is64 ? idx32[2 * i] : idx32[i];

    const uint4*  rowp = reinterpret_cast<const uint4*>(ppr) + (size_t)row * (NN / 4);
    const float4* X4   = reinterpret_cast<const float4*>(X);
    const int base = warp * 1024;   // this warp's quarter: 1024 uint4 = 16KB

    // ---- Stage 1: scan with inline processing (2 ballots per uint4) ----
    float4 acc = make_float4(0.f, 0.f, 0.f, 0.f);
    float  srow = 0.0f;

    for (int it = 0; it < 32; it += 8) {
        uint4 buf[8];
#pragma unroll
        for (int u = 0; u < 8; u++)
            buf[u] = __ldcs(rowp + base + (it + u) * 32 + lane);

#pragma unroll
        for (int u = 0; u < 8; u++) {
            const uint4 q = buf[u];
            const int j0 = (base + (it + u) * 32 + lane) * 4;

            // pair (x, y): columns j0, j0+1
            unsigned m = __ballot_sync(0xffffffffu, (q.x | q.y) != 0u);
            while (m) {
                const int src = __ffs(m) - 1;
                m &= m - 1;
                const float vx = __shfl_sync(0xffffffffu, __uint_as_float(q.x), src);
                const float vy = __shfl_sync(0xffffffffu, __uint_as_float(q.y), src);
                const int   js = __shfl_sync(0xffffffffu, j0, src);
                if (vx != 0.0f) { const float4 xr = __ldg(X4 + (size_t)js * 32 + lane);
                                  acc.x += vx*xr.x; acc.y += vx*xr.y; acc.z += vx*xr.z; acc.w += vx*xr.w; srow += vx; }
                if (vy != 0.0f) { const float4 xr = __ldg(X4 + (size_t)(js + 1) * 32 + lane);
                                  acc.x += vy*xr.x; acc.y += vy*xr.y; acc.z += vy*xr.z; acc.w += vy*xr.w; srow += vy; }
            }

            // pair (z, w): columns j0+2, j0+3
            m = __ballot_sync(0xffffffffu, (q.z | q.w) != 0u);
            while (m) {
                const int src = __ffs(m) - 1;
                m &= m - 1;
                const float vz = __shfl_sync(0xffffffffu, __uint_as_float(q.z), src);
                const float vw = __shfl_sync(0xffffffffu, __uint_as_float(q.w), src);
                const int   js = __shfl_sync(0xffffffffu, j0, src);
                if (vz != 0.0f) { const float4 xr = __ldg(X4 + (size_t)(js + 2) * 32 + lane);
                                  acc.x += vz*xr.x; acc.y += vz*xr.y; acc.z += vz*xr.z; acc.w += vz*xr.w; srow += vz; }
                if (vw != 0.0f) { const float4 xr = __ldg(X4 + (size_t)(js + 3) * 32 + lane);
                                  acc.x += vw*xr.x; acc.y += vw*xr.y; acc.z += vw*xr.z; acc.w += vw*xr.w; srow += vw; }
            }
        }
    }

    reinterpret_cast<float4*>(red[warp])[lane] = acc;
    if (lane == 0) rsum[warp] = srow;
    __syncthreads();

    // ---- Stage 2: combine warps; thread c owns t-column c ----
    sT[tid] = red[0][tid] + red[1][tid] + red[2][tid] + red[3][tid];
    __syncthreads();

    // ---- Stage 3: epilogue — out = sT @ W + rowsum*b ----
    {
        const int cq = tid & 15;          // column quad (4 cols each)
        const int kg = tid >> 4;          // k-group of 16
        const float4* W4 = reinterpret_cast<const float4*>(W);  // W4[k*16 + cq]
        float4 a4 = make_float4(0.f, 0.f, 0.f, 0.f);
#pragma unroll
        for (int kk = 0; kk < 16; kk++) {
            const int k = kg * 16 + kk;
            const float tv = sT[k];
            const float4 w4 = __ldg(W4 + k * 16 + cq);
            a4.x += tv * w4.x; a4.y += tv * w4.y;
            a4.z += tv * w4.z; a4.w += tv * w4.w;
        }
        reinterpret_cast<float4*>(part[kg])[cq] = a4;
        __syncthreads();
        if (tid < D_H) {
            const float rs = rsum[0] + rsum[1] + rsum[2] + rsum[3];
            float s = rs * __ldg(b + tid);
#pragma unroll
            for (int g = 0; g < 8; g++) s += part[g][tid];
            out[(size_t)i * D_H + tid] = s;
        }
    }
}

// ---------------------------------------------------------------------------
extern "C" void kernel_launch(void* const* d_in, const int* in_sizes, int n_in,
                              void* d_out, int out_size) {
    const float* X   = (const float*)d_in[0];
    const float* ppr = (const float*)d_in[1];
    const float* W   = (const float*)d_in[2];
    const float* b   = (const float*)d_in[3];
    const int*   idx = (const int*)d_in[4];
    float* out = (float*)d_out;

    fused_kernel<<<BB, 128>>>(ppr, X, W, b, idx, out);
}

// round 17
// speedup vs baseline: 1.1123x; 1.1123x over previous
#include <cuda_runtime.h>
#include <cstdint>

// Problem constants (fixed by reference)
#define NN    16384   // n_nodes
#define D_IN  128
#define D_H   64
#define BB    4096    // minibatch

// ---------------------------------------------------------------------------
// Single fused kernel: one block (4 warps) per output row.
//   out[i,:] = ppr[idx[i],:] @ (X @ W + b)
//            = (ppr_row_sparse @ X) @ W + rowsum * b     (TOPK<=128 nonzeros)
//
//  0. idx dtype detect (odd words of entries 0..255 — in-bounds for both
//     int32 [4096 words] and int64 [8192 words]; P(false|int32)~0).
//  1. Scan + inline process (R14 structure — the measured best at 57.0us):
//     per warp 8 uint4 in flight (__ldcs); per scalar, ballot finds the rare
//     nonzeros; (v, j) broadcast by shfl; every lane does
//     acc4 += v * X4[j*32+lane] (coalesced 512B L2-hot read of X row j).
//     NEW (zero-liveness tweak): one __any_sync on the uint4's integer-OR
//     skips all 4 per-scalar ballots when the warp's 128 floats are all zero
//     (~36% of batch elements; values nonneg, zeros exact +0.0f).
//     R15/R16 ballot reshapes both regressed via register growth (70/64 vs
//     56) — bodies here are byte-identical to R14, no new live values.
//  2. Combine warps -> sT[128], rowsum.
//  3. Epilogue (validated R13): thread = (column-quad, k-group): 16 LDG.128
//     of W + 64 FMA, smem k-group reduction, + rowsum*b.
// ---------------------------------------------------------------------------
__global__ void __launch_bounds__(128) fused_kernel(const float* __restrict__ ppr,
                                                    const float* __restrict__ X,
                                                    const float* __restrict__ W,
                                                    const float* __restrict__ b,
                                                    const int* __restrict__ idx32,
                                                    float* __restrict__ out) {
    __shared__ float red[4][D_IN];
    __shared__ float rsum[4];
    __shared__ float sT[D_IN];
    __shared__ float part[8][D_H];     // k-group partials
    __shared__ int   s_is64;

    const int i    = blockIdx.x;
    const int tid  = threadIdx.x;
    const int lane = tid & 31;
    const int warp = tid >> 5;

    // ---- Stage 0: dtype detect + row fetch ----
    if (tid == 0) s_is64 = 1;
    __syncthreads();
    if ((idx32[2 * tid + 1] | idx32[2 * (tid + 128) + 1]) != 0) s_is64 = 0;
    __syncthreads();
    const int row = s_is64 ? idx32[2 * i] : idx32[i];

    const uint4*  rowp = reinterpret_cast<const uint4*>(ppr) + (size_t)row * (NN / 4);
    const float4* X4   = reinterpret_cast<const float4*>(X);
    const int base = warp * 1024;   // this warp's quarter: 1024 uint4 = 16KB

    // ---- Stage 1: scan with inline processing ----
    float4 acc = make_float4(0.f, 0.f, 0.f, 0.f);
    float  srow = 0.0f;

    for (int it = 0; it < 32; it += 8) {
        uint4 buf[8];
#pragma unroll
        for (int u = 0; u < 8; u++)
            buf[u] = __ldcs(rowp + base + (it + u) * 32 + lane);

#pragma unroll
        for (int u = 0; u < 8; u++) {
            const uint4 q = buf[u];
            if (!__any_sync(0xffffffffu, (q.x | q.y | q.z | q.w) != 0u))
                continue;   // warp-uniform skip (~36% of batch elements)
            const int j0 = (base + (it + u) * 32 + lane) * 4;
            float vs[4] = {__uint_as_float(q.x), __uint_as_float(q.y),
                           __uint_as_float(q.z), __uint_as_float(q.w)};
#pragma unroll
            for (int e = 0; e < 4; e++) {
                unsigned m = __ballot_sync(0xffffffffu, vs[e] != 0.0f);
                while (m) {
                    const int src = __ffs(m) - 1;
                    m &= m - 1;
                    const float v = __shfl_sync(0xffffffffu, vs[e], src);
                    const int   j = __shfl_sync(0xffffffffu, j0 + e, src);
                    const float4 xr = __ldg(X4 + (size_t)j * 32 + lane);
                    acc.x += v * xr.x; acc.y += v * xr.y;
                    acc.z += v * xr.z; acc.w += v * xr.w;
                    srow += v;
                }
            }
        }
    }

    reinterpret_cast<float4*>(red[warp])[lane] = acc;
    if (lane == 0) rsum[warp] = srow;
    __syncthreads();

    // ---- Stage 2: combine warps; thread c owns t-column c ----
    sT[tid] = red[0][tid] + red[1][tid] + red[2][tid] + red[3][tid];
    __syncthreads();

    // ---- Stage 3: epilogue — out = sT @ W + rowsum*b ----
    {
        const int cq = tid & 15;          // column quad (4 cols each)
        const int kg = tid >> 4;          // k-group of 16
        const float4* W4 = reinterpret_cast<const float4*>(W);  // W4[k*16 + cq]
        float4 a4 = make_float4(0.f, 0.f, 0.f, 0.f);
#pragma unroll
        for (int kk = 0; kk < 16; kk++) {
            const int k = kg * 16 + kk;
            const float tv = sT[k];
            const float4 w4 = __ldg(W4 + k * 16 + cq);
            a4.x += tv * w4.x; a4.y += tv * w4.y;
            a4.z += tv * w4.z; a4.w += tv * w4.w;
        }
        reinterpret_cast<float4*>(part[kg])[cq] = a4;
        __syncthreads();
        if (tid < D_H) {
            const float rs = rsum[0] + rsum[1] + rsum[2] + rsum[3];
            float s = rs * __ldg(b + tid);
#pragma unroll
            for (int g = 0; g < 8; g++) s += part[g][tid];
            out[(size_t)i * D_H + tid] = s;
        }
    }
}

// ---------------------------------------------------------------------------
extern "C" void kernel_launch(void* const* d_in, const int* in_sizes, int n_in,
                              void* d_out, int out_size) {
    const float* X   = (const float*)d_in[0];
    const float* ppr = (const float*)d_in[1];
    const float* W   = (const float*)d_in[2];
    const float* b   = (const float*)d_in[3];
    const int*   idx = (const int*)d_in[4];
    float* out = (float*)d_out;

    fused_kernel<<<BB, 128>>>(ppr, X, W, b, idx, out);
}